// round 11
// baseline (speedup 1.0000x reference)
#include <cuda_runtime.h>
#include <cuda_bf16.h>
#include <cstdint>

// Problem: BS=32, SEQ_LEN=4096, HIDDEN=1024
//   prefix[b]  = first index where attention_mask[b,:] == 0, else 4096
//   n_valid[b] = max(prefix[b]-1, 1)
//   u[b,e]     = jax.random.uniform(key(42), (32,1024))
//                (threefry2x32, PARTITIONABLE scheme: counter = linear idx,
//                 x0 = hi32 = 0, x1 = lo32 = i, bits = y0 ^ y1)
//   idx[b,e]   = min(int(u*n_valid), n_valid-1)
//   out[b,e]   = tokens[b, idx[b,e], e]

static constexpr int BS = 32;
static constexpr int SEQ_LEN = 4096;
static constexpr int HIDDEN = 1024;

// ---- JAX threefry2x32 (20 rounds), key = (0, 42) ----
__device__ __forceinline__ uint32_t rotl32(uint32_t x, int d) {
    return (x << d) | (x >> (32 - d));
}

__device__ __forceinline__ void threefry2x32(uint32_t k0, uint32_t k1,
                                             uint32_t& x0, uint32_t& x1) {
    const uint32_t ks2 = k0 ^ k1 ^ 0x1BD11BDAu;
    x0 += k0; x1 += k1;

#define TF_R4(a, b, c, d)                                        \
    x0 += x1; x1 = rotl32(x1, a); x1 ^= x0;                       \
    x0 += x1; x1 = rotl32(x1, b); x1 ^= x0;                       \
    x0 += x1; x1 = rotl32(x1, c); x1 ^= x0;                       \
    x0 += x1; x1 = rotl32(x1, d); x1 ^= x0;

    TF_R4(13, 15, 26, 6);   x0 += k1;  x1 += ks2 + 1u;
    TF_R4(17, 29, 16, 24);  x0 += ks2; x1 += k0  + 2u;
    TF_R4(13, 15, 26, 6);   x0 += k0;  x1 += k1  + 3u;
    TF_R4(17, 29, 16, 24);  x0 += k1;  x1 += ks2 + 4u;
    TF_R4(13, 15, 26, 6);   x0 += ks2; x1 += k0  + 5u;
#undef TF_R4
}

__global__ __launch_bounds__(1024, 1)
void condensed_embracement_kernel(const float* __restrict__ tokens,
                                  const int*   __restrict__ mask,
                                  float*       __restrict__ out) {
    const int b   = blockIdx.x;     // 0..31
    const int tid = threadIdx.x;    // 0..1023 (one per embedding channel)

    __shared__ int s_prefix;
    if (tid == 0) s_prefix = SEQ_LEN;
    __syncthreads();

    // ---- prefix = first zero in mask[b,:] (one LDG.128 per thread) ----
    const int4* m4 = (const int4*)(mask + (size_t)b * SEQ_LEN);
    int4 v = m4[tid];
    int local_first = SEQ_LEN;
    if (v.w == 0) local_first = 4 * tid + 3;
    if (v.z == 0) local_first = 4 * tid + 2;
    if (v.y == 0) local_first = 4 * tid + 1;
    if (v.x == 0) local_first = 4 * tid + 0;
    if (local_first < SEQ_LEN) atomicMin(&s_prefix, local_first);
    __syncthreads();

    const int prefix  = s_prefix;
    const int n_valid = max(prefix - 1, 1);

    // ---- threefry (partitionable scheme) for linear index n = b*HIDDEN+tid ----
    // counter = uint64(n): x0 = hi32 = 0, x1 = lo32 = n; bits = y0 ^ y1
    const int n = b * HIDDEN + tid;
    uint32_t x0 = 0u, x1 = (uint32_t)n;
    threefry2x32(0u, 42u, x0, x1);
    const uint32_t bits = x0 ^ x1;

    // uniform in [0,1): bitcast((bits >> 9) | 0x3f800000) - 1.0, then max(0, .)
    float u = __uint_as_float((bits >> 9) | 0x3f800000u) - 1.0f;
    u = fmaxf(u, 0.0f);

    int idx = (int)(u * (float)n_valid);   // trunc toward zero, matches astype(int32)
    idx = min(idx, n_valid - 1);

    // ---- gather ----
    out[(size_t)b * HIDDEN + tid] =
        tokens[((size_t)b * SEQ_LEN + idx) * HIDDEN + tid];
}

extern "C" void kernel_launch(void* const* d_in, const int* in_sizes, int n_in,
                              void* d_out, int out_size) {
    // Robust input selection: tokens has 32*4096*1024 elems, mask has 32*4096.
    const float* tokens;
    const int*   mask;
    if (n_in >= 2 && in_sizes[0] >= in_sizes[1]) {
        tokens = (const float*)d_in[0];
        mask   = (const int*)d_in[1];
    } else {
        tokens = (const float*)d_in[1];
        mask   = (const int*)d_in[0];
    }
    float* out = (float*)d_out;
    (void)out_size;

    condensed_embracement_kernel<<<BS, 1024>>>(tokens, mask, out);
}

// round 13
// speedup vs baseline: 1.0048x; 1.0048x over previous
#include <cuda_runtime.h>
#include <cuda_bf16.h>
#include <cstdint>

// BS=32, SEQ_LEN=4096, HIDDEN=1024
// prefix[b] = first zero in mask[b,:] (mask rows are monotone 1...10...0)
// n_valid = max(prefix-1, 1)
// bits[i] = fold(threefry2x32(key=(0,42), counter=(0,i))) (JAX partitionable)
// u = bitcast((bits>>9)|0x3f800000)-1, clamped at 0
// idx = min(int(u*n_valid), n_valid-1); out[b,e] = tokens[b, idx, e]

static constexpr int BS = 32;
static constexpr int SEQ_LEN = 4096;
static constexpr int HIDDEN = 1024;
static constexpr int SLICES = 8;            // CTAs per batch
static constexpr int THREADS = 128;         // channels per CTA
static constexpr int INT4_PER_THREAD = SEQ_LEN / (4 * THREADS);  // 8

// ---- JAX threefry2x32 (20 rounds), key = (0, 42) ----
__device__ __forceinline__ uint32_t rotl32(uint32_t x, int d) {
    return (x << d) | (x >> (32 - d));
}

__device__ __forceinline__ void threefry2x32(uint32_t k0, uint32_t k1,
                                             uint32_t& x0, uint32_t& x1) {
    const uint32_t ks2 = k0 ^ k1 ^ 0x1BD11BDAu;
    x0 += k0; x1 += k1;

#define TF_R4(a, b, c, d)                                        \
    x0 += x1; x1 = rotl32(x1, a); x1 ^= x0;                       \
    x0 += x1; x1 = rotl32(x1, b); x1 ^= x0;                       \
    x0 += x1; x1 = rotl32(x1, c); x1 ^= x0;                       \
    x0 += x1; x1 = rotl32(x1, d); x1 ^= x0;

    TF_R4(13, 15, 26, 6);   x0 += k1;  x1 += ks2 + 1u;
    TF_R4(17, 29, 16, 24);  x0 += ks2; x1 += k0  + 2u;
    TF_R4(13, 15, 26, 6);   x0 += k0;  x1 += k1  + 3u;
    TF_R4(17, 29, 16, 24);  x0 += k1;  x1 += ks2 + 4u;
    TF_R4(13, 15, 26, 6);   x0 += ks2; x1 += k0  + 5u;
#undef TF_R4
}

__global__ __launch_bounds__(THREADS, 8)
void condensed_embracement_kernel(const float* __restrict__ tokens,
                                  const int*   __restrict__ mask,
                                  float*       __restrict__ out) {
    const int slice = blockIdx.x;        // 0..7  (128-channel slice)
    const int b     = blockIdx.y;        // 0..31 (batch)
    const int tid   = threadIdx.x;       // 0..127

    __shared__ int s_prefix;
    if (tid == 0) s_prefix = SEQ_LEN;

    // ---- issue all mask loads up front (MLP=8, coalesced int4) ----
    const int4* m4 = (const int4*)(mask + (size_t)b * SEQ_LEN);
    int4 v[INT4_PER_THREAD];
#pragma unroll
    for (int i = 0; i < INT4_PER_THREAD; i++) {
        v[i] = m4[tid + i * THREADS];    // element index: 4*(tid + i*128)
    }

    // ---- threefry while loads are in flight (independent ALU work) ----
    const int c = slice * THREADS + tid;          // channel 0..1023
    const int n = b * HIDDEN + c;                 // linear PRNG index
    uint32_t x0 = 0u, x1 = (uint32_t)n;
    threefry2x32(0u, 42u, x0, x1);
    const uint32_t bits = x0 ^ x1;
    float u = __uint_as_float((bits >> 9) | 0x3f800000u) - 1.0f;
    u = fmaxf(u, 0.0f);

    // ---- first-zero reduction ----
    int local_first = SEQ_LEN;
#pragma unroll
    for (int i = INT4_PER_THREAD - 1; i >= 0; i--) {
        const int base = 4 * (tid + i * THREADS);
        if (v[i].w == 0) local_first = base + 3;
        if (v[i].z == 0) local_first = base + 2;
        if (v[i].y == 0) local_first = base + 1;
        if (v[i].x == 0) local_first = base + 0;
    }
    __syncthreads();                      // s_prefix initialized
    int warp_min = __reduce_min_sync(0xFFFFFFFFu, local_first);
    if ((tid & 31) == 0 && warp_min < SEQ_LEN) atomicMin(&s_prefix, warp_min);
    __syncthreads();

    const int n_valid = max(s_prefix - 1, 1);

    int idx = (int)(u * (float)n_valid);  // trunc toward zero == astype(int32)
    idx = min(idx, n_valid - 1);

    // ---- gather + coalesced store ----
    out[(size_t)b * HIDDEN + c] =
        tokens[((size_t)b * SEQ_LEN + idx) * HIDDEN + c];
}

extern "C" void kernel_launch(void* const* d_in, const int* in_sizes, int n_in,
                              void* d_out, int out_size) {
    // tokens: 32*4096*1024 elems, mask: 32*4096 elems
    const float* tokens;
    const int*   mask;
    if (n_in >= 2 && in_sizes[0] >= in_sizes[1]) {
        tokens = (const float*)d_in[0];
        mask   = (const int*)d_in[1];
    } else {
        tokens = (const float*)d_in[1];
        mask   = (const int*)d_in[0];
    }
    float* out = (float*)d_out;
    (void)out_size;

    dim3 grid(SLICES, BS);
    condensed_embracement_kernel<<<grid, THREADS>>>(tokens, mask, out);
}